// round 4
// baseline (speedup 1.0000x reference)
#include <cuda_runtime.h>
#include <math.h>

#define BB   4
#define SS   2048
#define HH   16
#define DEP  64
#define DM   1024
#define MR   (BB*SS)   // 8192 rows

// Scratch (device globals: allocation-free per harness rules). 32 MB each.
__device__ float g_q[(size_t)MR*DM];
__device__ float g_k[(size_t)MR*DM];
__device__ float g_v[(size_t)MR*DM];
__device__ float g_ctx[(size_t)MR*DM];

// ---------------------------------------------------------------------------
// GEMM: C[M,N] = A[M,K] @ W[N,K]^T + bias  (K-major A and W, fp32)
// BM=128, BN=64, BK=16, 256 threads, 8x4 per-thread micro-tile.
// GATHER_A: A is read from head-split layout [(b,h),s,d] (for the dense proj)
// SPLIT_C : C is written to head-split layout [(b,h),s,d] (for Q/K/V proj)
// ---------------------------------------------------------------------------
template<bool GATHER_A, bool SPLIT_C>
__global__ void __launch_bounds__(256) gemm_kernel(const float* __restrict__ A,
                                                   const float* __restrict__ W,
                                                   const float* __restrict__ bias,
                                                   float* __restrict__ C)
{
    __shared__ float As[16][128];  // k-major (transposed on store)
    __shared__ float Ws[16][64];

    const int tid = threadIdx.x;
    const int tx = tid & 15, ty = tid >> 4;
    const int bm = blockIdx.x * 128;
    const int bn = blockIdx.y * 64;

    float acc[8][4];
#pragma unroll
    for (int i = 0; i < 8; i++)
#pragma unroll
        for (int j = 0; j < 4; j++) acc[i][j] = 0.f;

    for (int kt = 0; kt < DM; kt += 16) {
        // A tile: 128 rows x 16 k = 512 float4, 2 per thread
#pragma unroll
        for (int r = 0; r < 2; r++) {
            int f = tid + r * 256;
            int row = f >> 2, kq = f & 3;
            int m = bm + row, kk = kt + kq * 4;
            const float* src;
            if (GATHER_A) {
                int b = m >> 11, s = m & (SS - 1);
                int h = kk >> 6, d = kk & 63;
                src = &A[(((size_t)(b * HH + h)) * SS + s) * DEP + d];
            } else {
                src = &A[(size_t)m * DM + kk];
            }
            float4 v4 = *(const float4*)src;
            As[kq*4+0][row] = v4.x; As[kq*4+1][row] = v4.y;
            As[kq*4+2][row] = v4.z; As[kq*4+3][row] = v4.w;
        }
        // W tile: 64 rows x 16 k = 256 float4, 1 per thread
        {
            int row = tid >> 2, kq = tid & 3;
            float4 v4 = *(const float4*)&W[(size_t)(bn + row) * DM + kt + kq * 4];
            Ws[kq*4+0][row] = v4.x; Ws[kq*4+1][row] = v4.y;
            Ws[kq*4+2][row] = v4.z; Ws[kq*4+3][row] = v4.w;
        }
        __syncthreads();

#pragma unroll
        for (int k = 0; k < 16; k++) {
            float4 w4 = *(const float4*)&Ws[k][tx * 4];
            float4 a0 = *(const float4*)&As[k][ty * 8];
            float4 a1 = *(const float4*)&As[k][ty * 8 + 4];
            float a[8] = {a0.x, a0.y, a0.z, a0.w, a1.x, a1.y, a1.z, a1.w};
            float w[4] = {w4.x, w4.y, w4.z, w4.w};
#pragma unroll
            for (int i = 0; i < 8; i++)
#pragma unroll
                for (int j = 0; j < 4; j++)
                    acc[i][j] = fmaf(a[i], w[j], acc[i][j]);
        }
        __syncthreads();
    }

    const int n0 = bn + tx * 4;
    float4 bv = *(const float4*)&bias[n0];
#pragma unroll
    for (int i = 0; i < 8; i++) {
        int m = bm + ty * 8 + i;
        float4 o;
        o.x = acc[i][0] + bv.x; o.y = acc[i][1] + bv.y;
        o.z = acc[i][2] + bv.z; o.w = acc[i][3] + bv.w;
        if (SPLIT_C) {
            int b = m >> 11, s = m & (SS - 1);
            int h = n0 >> 6, d = n0 & 63;
            *(float4*)&C[(((size_t)(b * HH + h)) * SS + s) * DEP + d] = o;
        } else {
            *(float4*)&C[(size_t)m * DM + n0] = o;
        }
    }
}

// ---------------------------------------------------------------------------
// Flash-attention style kernel, fp32, per (b,h): 64-query tiles, loop 64-key
// tiles, online softmax. 256 threads, 4x4 per-thread micro-tile.
// Q pre-scaled by 1/sqrt(depth)=0.125 at load.
// ---------------------------------------------------------------------------
#define ATTN_SMEM ((64*68 + 64*64 + 64*64 + 64*68) * 4)

__global__ void __launch_bounds__(256) attn_kernel(const float* __restrict__ Q,
                                                   const float* __restrict__ K,
                                                   const float* __restrict__ V,
                                                   float* __restrict__ O)
{
    extern __shared__ float sm[];
    float* Qs = sm;              // [64][68] q-major (broadcast operand)
    float* Ks = Qs + 64 * 68;    // [64][64] d-major (vector operand)
    float* Vs = Ks + 64 * 64;    // [64][64] k-major (vector operand)
    float* Ps = Vs + 64 * 64;    // [64][68] q-major (broadcast operand)

    const int tid = threadIdx.x;
    const int tx = tid & 15, ty = tid >> 4;
    const int bh = blockIdx.y;
    const int q0 = blockIdx.x * 64;
    const float* Qg = Q + (size_t)bh * SS * DEP;
    const float* Kg = K + (size_t)bh * SS * DEP;
    const float* Vg = V + (size_t)bh * SS * DEP;

    // Load Q tile (scaled)
#pragma unroll
    for (int r = 0; r < 4; r++) {
        int f = tid + r * 256;
        int row = f >> 4, c4 = (f & 15) * 4;
        float4 v4 = *(const float4*)&Qg[(size_t)(q0 + row) * DEP + c4];
        v4.x *= 0.125f; v4.y *= 0.125f; v4.z *= 0.125f; v4.w *= 0.125f;
        *(float4*)&Qs[row * 68 + c4] = v4;
    }

    float mst[4], lst[4], oacc[4][4];
#pragma unroll
    for (int i = 0; i < 4; i++) {
        mst[i] = -1e30f; lst[i] = 0.f;
#pragma unroll
        for (int j = 0; j < 4; j++) oacc[i][j] = 0.f;
    }

    for (int kt = 0; kt < SS / 64; kt++) {
        __syncthreads();  // prior PV reads done before overwriting tiles
        int k0 = kt * 64;
#pragma unroll
        for (int r = 0; r < 4; r++) {
            int f = tid + r * 256;
            int n = f >> 4, dq = f & 15;
            float4 v4 = *(const float4*)&Kg[(size_t)(k0 + n) * DEP + dq * 4];
            Ks[(dq*4+0)*64 + n] = v4.x;
            Ks[(dq*4+1)*64 + n] = v4.y;
            Ks[(dq*4+2)*64 + n] = v4.z;
            Ks[(dq*4+3)*64 + n] = v4.w;
            float4 w4 = *(const float4*)&Vg[(size_t)(k0 + n) * DEP + dq * 4];
            *(float4*)&Vs[n * 64 + dq * 4] = w4;
        }
        __syncthreads();

        // S = Q K^T (already scaled)
        float sc[4][4];
#pragma unroll
        for (int i = 0; i < 4; i++)
#pragma unroll
            for (int j = 0; j < 4; j++) sc[i][j] = 0.f;

#pragma unroll 4
        for (int d = 0; d < 64; d += 4) {
            float4 a4[4], b4[4];
#pragma unroll
            for (int i = 0; i < 4; i++) a4[i] = *(const float4*)&Qs[(ty*4+i)*68 + d];
#pragma unroll
            for (int t = 0; t < 4; t++) b4[t] = *(const float4*)&Ks[(d+t)*64 + tx*4];
#pragma unroll
            for (int i = 0; i < 4; i++) {
                float av[4] = {a4[i].x, a4[i].y, a4[i].z, a4[i].w};
#pragma unroll
                for (int t = 0; t < 4; t++) {
                    sc[i][0] = fmaf(av[t], b4[t].x, sc[i][0]);
                    sc[i][1] = fmaf(av[t], b4[t].y, sc[i][1]);
                    sc[i][2] = fmaf(av[t], b4[t].z, sc[i][2]);
                    sc[i][3] = fmaf(av[t], b4[t].w, sc[i][3]);
                }
            }
        }

        // Online softmax update (row groups span 16 lanes: shfl_xor 8..1)
#pragma unroll
        for (int i = 0; i < 4; i++) {
            float mloc = fmaxf(fmaxf(sc[i][0], sc[i][1]), fmaxf(sc[i][2], sc[i][3]));
#pragma unroll
            for (int off = 8; off >= 1; off >>= 1)
                mloc = fmaxf(mloc, __shfl_xor_sync(0xffffffffu, mloc, off));
            float mnew = fmaxf(mst[i], mloc);
            float fct = __expf(mst[i] - mnew);
            mst[i] = mnew;
            float lloc = 0.f;
#pragma unroll
            for (int j = 0; j < 4; j++) {
                sc[i][j] = __expf(sc[i][j] - mnew);
                lloc += sc[i][j];
            }
#pragma unroll
            for (int off = 8; off >= 1; off >>= 1)
                lloc += __shfl_xor_sync(0xffffffffu, lloc, off);
            lst[i] = lst[i] * fct + lloc;
#pragma unroll
            for (int j = 0; j < 4; j++) oacc[i][j] *= fct;
        }

        // Stage P to smem
#pragma unroll
        for (int i = 0; i < 4; i++)
            *(float4*)&Ps[(ty*4+i)*68 + tx*4] =
                make_float4(sc[i][0], sc[i][1], sc[i][2], sc[i][3]);
        __syncthreads();

        // O += P V
#pragma unroll 4
        for (int kk = 0; kk < 64; kk += 4) {
            float4 a4[4], b4[4];
#pragma unroll
            for (int i = 0; i < 4; i++) a4[i] = *(const float4*)&Ps[(ty*4+i)*68 + kk];
#pragma unroll
            for (int t = 0; t < 4; t++) b4[t] = *(const float4*)&Vs[(kk+t)*64 + tx*4];
#pragma unroll
            for (int i = 0; i < 4; i++) {
                float av[4] = {a4[i].x, a4[i].y, a4[i].z, a4[i].w};
#pragma unroll
                for (int t = 0; t < 4; t++) {
                    oacc[i][0] = fmaf(av[t], b4[t].x, oacc[i][0]);
                    oacc[i][1] = fmaf(av[t], b4[t].y, oacc[i][1]);
                    oacc[i][2] = fmaf(av[t], b4[t].z, oacc[i][2]);
                    oacc[i][3] = fmaf(av[t], b4[t].w, oacc[i][3]);
                }
            }
        }
    }

    float* Og = O + (size_t)bh * SS * DEP;
#pragma unroll
    for (int i = 0; i < 4; i++) {
        float inv = 1.0f / lst[i];
        float4 o4 = make_float4(oacc[i][0]*inv, oacc[i][1]*inv,
                                oacc[i][2]*inv, oacc[i][3]*inv);
        *(float4*)&Og[(size_t)(q0 + ty*4 + i) * DEP + tx*4] = o4;
    }
}

// ---------------------------------------------------------------------------
extern "C" void kernel_launch(void* const* d_in, const int* in_sizes, int n_in,
                              void* d_out, int out_size)
{
    const float* query   = (const float*)d_in[0];
    const float* key     = (const float*)d_in[1];
    const float* value   = (const float*)d_in[2];
    const float* wq_w    = (const float*)d_in[3];
    const float* wq_b    = (const float*)d_in[4];
    const float* wk_w    = (const float*)d_in[5];
    const float* wk_b    = (const float*)d_in[6];
    const float* wv_w    = (const float*)d_in[7];
    const float* wv_b    = (const float*)d_in[8];
    const float* dense_w = (const float*)d_in[9];
    const float* dense_b = (const float*)d_in[10];
    float* out = (float*)d_out;

    float *qb, *kb, *vb, *cb;
    cudaGetSymbolAddress((void**)&qb, g_q);
    cudaGetSymbolAddress((void**)&kb, g_k);
    cudaGetSymbolAddress((void**)&vb, g_v);
    cudaGetSymbolAddress((void**)&cb, g_ctx);

    dim3 gg(MR / 128, DM / 64);
    gemm_kernel<false, true><<<gg, 256>>>(query, wq_w, wq_b, qb);
    gemm_kernel<false, true><<<gg, 256>>>(key,   wk_w, wk_b, kb);
    gemm_kernel<false, true><<<gg, 256>>>(value, wv_w, wv_b, vb);

    cudaFuncSetAttribute(attn_kernel,
                         cudaFuncAttributeMaxDynamicSharedMemorySize, ATTN_SMEM);
    dim3 ga(SS / 64, BB * HH);
    attn_kernel<<<ga, 256, ATTN_SMEM>>>(qb, kb, vb, cb);

    gemm_kernel<true, false><<<gg, 256>>>(cb, dense_w, dense_b, out);
}

// round 7
// speedup vs baseline: 2.7404x; 2.7404x over previous
#include <cuda_runtime.h>
#include <cuda_bf16.h>

#define BB   4
#define SS   2048
#define HH   16
#define DEP  64
#define DM   1024
#define MR   (BB*SS)   // 8192

// fp32 scratch (device globals: allocation-free per harness rules)
__device__ float g_q[(size_t)MR*DM];
__device__ float g_k[(size_t)MR*DM];
__device__ float g_v[(size_t)MR*DM];
__device__ float g_ctx[(size_t)MR*DM];

// ---------------- PTX helpers ----------------
__device__ __forceinline__ unsigned smaddr(const void* p) {
    return (unsigned)__cvta_generic_to_shared(p);
}
__device__ __forceinline__ void ldm4(unsigned r[4], const void* p) {
    unsigned a = smaddr(p);
    asm volatile("ldmatrix.sync.aligned.m8n8.x4.shared.b16 {%0,%1,%2,%3},[%4];\n"
                 : "=r"(r[0]), "=r"(r[1]), "=r"(r[2]), "=r"(r[3]) : "r"(a));
}
__device__ __forceinline__ void ldm4t(unsigned r[4], const void* p) {
    unsigned a = smaddr(p);
    asm volatile("ldmatrix.sync.aligned.m8n8.x4.trans.shared.b16 {%0,%1,%2,%3},[%4];\n"
                 : "=r"(r[0]), "=r"(r[1]), "=r"(r[2]), "=r"(r[3]) : "r"(a));
}
__device__ __forceinline__ void mma_bf(float c[4], const unsigned a[4], const unsigned b[2]) {
    asm volatile("mma.sync.aligned.m16n8k16.row.col.f32.bf16.bf16.f32 "
                 "{%0,%1,%2,%3},{%4,%5,%6,%7},{%8,%9},{%0,%1,%2,%3};\n"
                 : "+f"(c[0]), "+f"(c[1]), "+f"(c[2]), "+f"(c[3])
                 : "r"(a[0]), "r"(a[1]), "r"(a[2]), "r"(a[3]), "r"(b[0]), "r"(b[1]));
}
__device__ __forceinline__ unsigned pk(__nv_bfloat16 a, __nv_bfloat16 b) {
    return (unsigned)__bfloat16_as_ushort(a) | ((unsigned)__bfloat16_as_ushort(b) << 16);
}
// split two fp32 into packed bf16x2 hi and lo planes (elem0 in low half)
__device__ __forceinline__ void split2(float x, float y, unsigned& h, unsigned& l) {
    __nv_bfloat16 hx = __float2bfloat16(x), hy = __float2bfloat16(y);
    __nv_bfloat16 lx = __float2bfloat16(x - __bfloat162float(hx));
    __nv_bfloat16 ly = __float2bfloat16(y - __bfloat162float(hy));
    h = pk(hx, hy); l = pk(lx, ly);
}

// ---------------------------------------------------------------------------
// GEMM: C[M,N] = A[M,K] @ W[N,K]^T + bias via bf16-split mma.
// BM=128 BN=64 BK=32, 256 thr = 8 warps (4M x 2N), warp tile 32x32.
// ---------------------------------------------------------------------------
template<bool GATHER_A, bool SPLIT_C>
__global__ void __launch_bounds__(256) gemm_mma(const float* __restrict__ A,
                                               const float* __restrict__ W,
                                               const float* __restrict__ bias,
                                               float* __restrict__ C)
{
    __shared__ __nv_bfloat16 Ah[128][40], Al[128][40], Wh[64][40], Wl[64][40];
    const int tid = threadIdx.x, lane = tid & 31, warp = tid >> 5;
    const int wm = warp >> 1, wn = warp & 1;
    const int bm = blockIdx.x * 128, bn = blockIdx.y * 64;

    float acc[2][4][4];
#pragma unroll
    for (int i = 0; i < 2; i++)
#pragma unroll
        for (int j = 0; j < 4; j++)
#pragma unroll
            for (int k = 0; k < 4; k++) acc[i][j][k] = 0.f;

    for (int kt = 0; kt < DM; kt += 32) {
        __syncthreads();
        // stage A tile (128x32) with on-the-fly split
#pragma unroll
        for (int r = 0; r < 4; r++) {
            int f = tid + r * 256, row = f >> 3, c4 = (f & 7) * 4;
            int m = bm + row, kk = kt + c4;
            const float* src;
            if (GATHER_A) {
                int b = m >> 11, s = m & (SS - 1), h = kk >> 6, d = kk & 63;
                src = &A[(((size_t)(b * HH + h)) * SS + s) * DEP + d];
            } else {
                src = &A[(size_t)m * DM + kk];
            }
            float4 v = *(const float4*)src;
            unsigned h0, l0, h1, l1;
            split2(v.x, v.y, h0, l0); split2(v.z, v.w, h1, l1);
            *(uint2*)&Ah[row][c4] = make_uint2(h0, h1);
            *(uint2*)&Al[row][c4] = make_uint2(l0, l1);
        }
        // stage W tile (64x32)
#pragma unroll
        for (int r = 0; r < 2; r++) {
            int f = tid + r * 256, row = f >> 3, c4 = (f & 7) * 4;
            float4 v = *(const float4*)&W[(size_t)(bn + row) * DM + kt + c4];
            unsigned h0, l0, h1, l1;
            split2(v.x, v.y, h0, l0); split2(v.z, v.w, h1, l1);
            *(uint2*)&Wh[row][c4] = make_uint2(h0, h1);
            *(uint2*)&Wl[row][c4] = make_uint2(l0, l1);
        }
        __syncthreads();

#pragma unroll
        for (int ch = 0; ch < 2; ch++) {
            unsigned ah[2][4], al[2][4];
            int acol = ch * 16 + ((lane & 16) >> 1);
#pragma unroll
            for (int mt = 0; mt < 2; mt++) {
                int arow = wm * 32 + mt * 16 + (lane & 15);
                ldm4(ah[mt], &Ah[arow][acol]);
                ldm4(al[mt], &Al[arow][acol]);
            }
#pragma unroll
            for (int np = 0; np < 2; np++) {
                unsigned bhf[4], blf[4];
                int nrow = wn * 32 + np * 16 + (lane & 7) + ((lane & 16) >> 1);
                int kcol = ch * 16 + (lane & 8);
                ldm4(bhf, &Wh[nrow][kcol]);
                ldm4(blf, &Wl[nrow][kcol]);
#pragma unroll
                for (int mt = 0; mt < 2; mt++)
#pragma unroll
                    for (int s = 0; s < 2; s++) {
                        int nt = np * 2 + s;
                        mma_bf(acc[mt][nt], ah[mt], &bhf[s * 2]);
                        mma_bf(acc[mt][nt], al[mt], &bhf[s * 2]);
                        mma_bf(acc[mt][nt], ah[mt], &blf[s * 2]);
                    }
            }
        }
    }

    const int g = lane >> 2, tig = lane & 3;
#pragma unroll
    for (int mt = 0; mt < 2; mt++)
#pragma unroll
        for (int nt = 0; nt < 4; nt++) {
            int m0 = bm + wm * 32 + mt * 16 + g;
            int n0 = bn + wn * 32 + nt * 8 + tig * 2;
            float b0 = bias[n0], b1 = bias[n0 + 1];
            float2 vlo = make_float2(acc[mt][nt][0] + b0, acc[mt][nt][1] + b1);
            float2 vhi = make_float2(acc[mt][nt][2] + b0, acc[mt][nt][3] + b1);
            if (SPLIT_C) {
                int h = n0 >> 6, d = n0 & 63;
                int bb = m0 >> 11, s0 = m0 & (SS - 1);
                size_t base = ((size_t)(bb * HH + h)) * SS;
                *(float2*)&C[(base + s0) * DEP + d] = vlo;
                *(float2*)&C[(base + s0 + 8) * DEP + d] = vhi;
            } else {
                *(float2*)&C[(size_t)m0 * DM + n0] = vlo;
                *(float2*)&C[(size_t)(m0 + 8) * DM + n0] = vhi;
            }
        }
}

// ---------------------------------------------------------------------------
// Flash attention, bf16-split mma. 256 thr = 8 warps; q-tile 128 (16/warp),
// key tile 64, d = 64. S c-frags feed PV a-frags directly from registers.
// ---------------------------------------------------------------------------
#define ATTN_SMEM_BYTES ((2*128*72 + 4*64*72) * 2)  // 73728

__global__ void __launch_bounds__(256) attn_mma(const float* __restrict__ Q,
                                                const float* __restrict__ K,
                                                const float* __restrict__ V,
                                                float* __restrict__ O)
{
    extern __shared__ __nv_bfloat16 smb[];
    __nv_bfloat16* Qh = smb;
    __nv_bfloat16* Ql = Qh + 128 * 72;
    __nv_bfloat16* Kh = Ql + 128 * 72;
    __nv_bfloat16* Kl = Kh + 64 * 72;
    __nv_bfloat16* Vh = Kl + 64 * 72;
    __nv_bfloat16* Vl = Vh + 64 * 72;

    const int tid = threadIdx.x, lane = tid & 31, warp = tid >> 5;
    const int bh = blockIdx.y, q0 = blockIdx.x * 128;
    const float* Qg = Q + (size_t)bh * SS * DEP + (size_t)q0 * DEP;
    const float* Kg = K + (size_t)bh * SS * DEP;
    const float* Vg = V + (size_t)bh * SS * DEP;

    // stage Q (scaled by 1/8), split
#pragma unroll
    for (int r = 0; r < 8; r++) {
        int f = tid + r * 256, row = f >> 4, c4 = (f & 15) * 4;
        float4 v = *(const float4*)&Qg[row * 64 + c4];
        v.x *= 0.125f; v.y *= 0.125f; v.z *= 0.125f; v.w *= 0.125f;
        unsigned h0, l0, h1, l1;
        split2(v.x, v.y, h0, l0); split2(v.z, v.w, h1, l1);
        *(uint2*)&Qh[row * 72 + c4] = make_uint2(h0, h1);
        *(uint2*)&Ql[row * 72 + c4] = make_uint2(l0, l1);
    }

    float oacc[8][4];
#pragma unroll
    for (int i = 0; i < 8; i++)
#pragma unroll
        for (int j = 0; j < 4; j++) oacc[i][j] = 0.f;
    float mst[2] = {-1e30f, -1e30f}, lst[2] = {0.f, 0.f};
    const int g = lane >> 2, tig = lane & 3;

    for (int kt = 0; kt < SS / 64; kt++) {
        __syncthreads();
        // stage K,V tiles (64x64 each), split
#pragma unroll
        for (int r = 0; r < 4; r++) {
            int f = tid + r * 256, row = f >> 4, c4 = (f & 15) * 4;
            int goff = (kt * 64 + row) * 64 + c4;
            float4 v = *(const float4*)&Kg[goff];
            unsigned h0, l0, h1, l1;
            split2(v.x, v.y, h0, l0); split2(v.z, v.w, h1, l1);
            *(uint2*)&Kh[row * 72 + c4] = make_uint2(h0, h1);
            *(uint2*)&Kl[row * 72 + c4] = make_uint2(l0, l1);
            float4 w = *(const float4*)&Vg[goff];
            split2(w.x, w.y, h0, l0); split2(w.z, w.w, h1, l1);
            *(uint2*)&Vh[row * 72 + c4] = make_uint2(h0, h1);
            *(uint2*)&Vl[row * 72 + c4] = make_uint2(l0, l1);
        }
        __syncthreads();

        // S = Q K^T
        float sc[8][4];
#pragma unroll
        for (int i = 0; i < 8; i++)
#pragma unroll
            for (int j = 0; j < 4; j++) sc[i][j] = 0.f;

#pragma unroll
        for (int ch = 0; ch < 4; ch++) {   // d chunks of 16
            unsigned ah[4], al[4];
            int arow = warp * 16 + (lane & 15);
            int acol = ch * 16 + ((lane & 16) >> 1);
            ldm4(ah, &Qh[arow * 72 + acol]);
            ldm4(al, &Ql[arow * 72 + acol]);
#pragma unroll
            for (int np = 0; np < 4; np++) {
                unsigned bhf[4], blf[4];
                int nrow = np * 16 + (lane & 7) + ((lane & 16) >> 1);
                int kcol = ch * 16 + (lane & 8);
                ldm4(bhf, &Kh[nrow * 72 + kcol]);
                ldm4(blf, &Kl[nrow * 72 + kcol]);
#pragma unroll
                for (int s = 0; s < 2; s++) {
                    int nt = np * 2 + s;
                    mma_bf(sc[nt], ah, &bhf[s * 2]);
                    mma_bf(sc[nt], al, &bhf[s * 2]);
                    mma_bf(sc[nt], ah, &blf[s * 2]);
                }
            }
        }

        // online softmax: thread owns rows g (half 0) and g+8 (half 1)
#pragma unroll
        for (int hf = 0; hf < 2; hf++) {
            float mloc = -1e30f;
#pragma unroll
            for (int nt = 0; nt < 8; nt++)
                mloc = fmaxf(mloc, fmaxf(sc[nt][hf * 2], sc[nt][hf * 2 + 1]));
            mloc = fmaxf(mloc, __shfl_xor_sync(0xffffffffu, mloc, 1));
            mloc = fmaxf(mloc, __shfl_xor_sync(0xffffffffu, mloc, 2));
            float mnew = fmaxf(mst[hf], mloc);
            float fct = __expf(mst[hf] - mnew);
            mst[hf] = mnew;
            float lloc = 0.f;
#pragma unroll
            for (int nt = 0; nt < 8; nt++) {
                float e0 = __expf(sc[nt][hf * 2] - mnew);
                float e1 = __expf(sc[nt][hf * 2 + 1] - mnew);
                sc[nt][hf * 2] = e0; sc[nt][hf * 2 + 1] = e1;
                lloc += e0 + e1;
            }
            lloc += __shfl_xor_sync(0xffffffffu, lloc, 1);
            lloc += __shfl_xor_sync(0xffffffffu, lloc, 2);
            lst[hf] = lst[hf] * fct + lloc;
#pragma unroll
            for (int dt = 0; dt < 8; dt++) {
                oacc[dt][hf * 2] *= fct;
                oacc[dt][hf * 2 + 1] *= fct;
            }
        }

        // O += P V  (P a-frags built directly from S c-frags in registers)
#pragma unroll
        for (int ch = 0; ch < 4; ch++) {   // key chunks of 16
            unsigned ph[4], pl[4];
            split2(sc[ch * 2][0],     sc[ch * 2][1],     ph[0], pl[0]);
            split2(sc[ch * 2][2],     sc[ch * 2][3],     ph[1], pl[1]);
            split2(sc[ch * 2 + 1][0], sc[ch * 2 + 1][1], ph[2], pl[2]);
            split2(sc[ch * 2 + 1][2], sc[ch * 2 + 1][3], ph[3], pl[3]);
#pragma unroll
            for (int dp = 0; dp < 4; dp++) {
                unsigned vhf[4], vlf[4];
                int krow = ch * 16 + (lane & 7) + (lane & 8);
                int dcol = dp * 16 + ((lane & 16) >> 1);
                ldm4t(vhf, &Vh[krow * 72 + dcol]);
                ldm4t(vlf, &Vl[krow * 72 + dcol]);
#pragma unroll
                for (int s = 0; s < 2; s++) {
                    int dt = dp * 2 + s;
                    mma_bf(oacc[dt], ph, &vhf[s * 2]);
                    mma_bf(oacc[dt], pl, &vhf[s * 2]);
                    mma_bf(oacc[dt], ph, &vlf[s * 2]);
                }
            }
        }
    }

    float inv0 = 1.0f / lst[0], inv1 = 1.0f / lst[1];
    float* Og = O + (size_t)bh * SS * DEP + (size_t)q0 * DEP;
    int r0 = warp * 16 + g;
#pragma unroll
    for (int dt = 0; dt < 8; dt++) {
        int col = dt * 8 + tig * 2;
        *(float2*)&Og[r0 * 64 + col] =
            make_float2(oacc[dt][0] * inv0, oacc[dt][1] * inv0);
        *(float2*)&Og[(r0 + 8) * 64 + col] =
            make_float2(oacc[dt][2] * inv1, oacc[dt][3] * inv1);
    }
}

// ---------------------------------------------------------------------------
extern "C" void kernel_launch(void* const* d_in, const int* in_sizes, int n_in,
                              void* d_out, int out_size)
{
    const float* query   = (const float*)d_in[0];
    const float* key     = (const float*)d_in[1];
    const float* value   = (const float*)d_in[2];
    const float* wq_w    = (const float*)d_in[3];
    const float* wq_b    = (const float*)d_in[4];
    const float* wk_w    = (const float*)d_in[5];
    const float* wk_b    = (const float*)d_in[6];
    const float* wv_w    = (const float*)d_in[7];
    const float* wv_b    = (const float*)d_in[8];
    const float* dense_w = (const float*)d_in[9];
    const float* dense_b = (const float*)d_in[10];
    float* out = (float*)d_out;

    float *qb, *kb, *vb, *cb;
    cudaGetSymbolAddress((void**)&qb, g_q);
    cudaGetSymbolAddress((void**)&kb, g_k);
    cudaGetSymbolAddress((void**)&vb, g_v);
    cudaGetSymbolAddress((void**)&cb, g_ctx);

    dim3 gg(MR / 128, DM / 64);
    gemm_mma<false, true><<<gg, 256>>>(query, wq_w, wq_b, qb);
    gemm_mma<false, true><<<gg, 256>>>(key,   wk_w, wk_b, kb);
    gemm_mma<false, true><<<gg, 256>>>(value, wv_w, wv_b, vb);

    cudaFuncSetAttribute(attn_mma,
                         cudaFuncAttributeMaxDynamicSharedMemorySize,
                         ATTN_SMEM_BYTES);
    dim3 ga(SS / 128, BB * HH);
    attn_mma<<<ga, 256, ATTN_SMEM_BYTES>>>(qb, kb, vb, cb);

    gemm_mma<true, false><<<gg, 256>>>(cb, dense_w, dense_b, out);
}

// round 8
// speedup vs baseline: 3.0918x; 1.1282x over previous
#include <cuda_runtime.h>
#include <cuda_bf16.h>

#define BB   4
#define SS   2048
#define HH   16
#define DEP  64
#define DM   1024
#define MR   (BB*SS)   // 8192

typedef __nv_bfloat16 bf16;

// ---------------- persistent bf16 hi/lo planes (device globals) ----------------
__device__ bf16 g_xq_h[(size_t)MR*DM], g_xq_l[(size_t)MR*DM];
__device__ bf16 g_xk_h[(size_t)MR*DM], g_xk_l[(size_t)MR*DM];
__device__ bf16 g_xv_h[(size_t)MR*DM], g_xv_l[(size_t)MR*DM];
__device__ bf16 g_wq_h[(size_t)DM*DM], g_wq_l[(size_t)DM*DM];
__device__ bf16 g_wk_h[(size_t)DM*DM], g_wk_l[(size_t)DM*DM];
__device__ bf16 g_wv_h[(size_t)DM*DM], g_wv_l[(size_t)DM*DM];
__device__ bf16 g_wd_h[(size_t)DM*DM], g_wd_l[(size_t)DM*DM];
__device__ bf16 g_Qh[(size_t)MR*DM], g_Ql[(size_t)MR*DM];   // head-split
__device__ bf16 g_Kh[(size_t)MR*DM], g_Kl[(size_t)MR*DM];   // head-split
__device__ bf16 g_Vh[(size_t)MR*DM], g_Vl[(size_t)MR*DM];   // head-split
__device__ bf16 g_Ch[(size_t)MR*DM], g_Cl[(size_t)MR*DM];   // head-split ctx

// ---------------- PTX helpers ----------------
__device__ __forceinline__ unsigned smaddr(const void* p) {
    return (unsigned)__cvta_generic_to_shared(p);
}
__device__ __forceinline__ void ldm4(unsigned r[4], const void* p) {
    unsigned a = smaddr(p);
    asm volatile("ldmatrix.sync.aligned.m8n8.x4.shared.b16 {%0,%1,%2,%3},[%4];\n"
                 : "=r"(r[0]), "=r"(r[1]), "=r"(r[2]), "=r"(r[3]) : "r"(a));
}
__device__ __forceinline__ void ldm4t(unsigned r[4], const void* p) {
    unsigned a = smaddr(p);
    asm volatile("ldmatrix.sync.aligned.m8n8.x4.trans.shared.b16 {%0,%1,%2,%3},[%4];\n"
                 : "=r"(r[0]), "=r"(r[1]), "=r"(r[2]), "=r"(r[3]) : "r"(a));
}
__device__ __forceinline__ void mma_bf(float c[4], const unsigned a[4], const unsigned b[2]) {
    asm volatile("mma.sync.aligned.m16n8k16.row.col.f32.bf16.bf16.f32 "
                 "{%0,%1,%2,%3},{%4,%5,%6,%7},{%8,%9},{%0,%1,%2,%3};\n"
                 : "+f"(c[0]), "+f"(c[1]), "+f"(c[2]), "+f"(c[3])
                 : "r"(a[0]), "r"(a[1]), "r"(a[2]), "r"(a[3]), "r"(b[0]), "r"(b[1]));
}
__device__ __forceinline__ unsigned pk(bf16 a, bf16 b) {
    return (unsigned)__bfloat16_as_ushort(a) | ((unsigned)__bfloat16_as_ushort(b) << 16);
}
__device__ __forceinline__ void split2(float x, float y, unsigned& h, unsigned& l) {
    bf16 hx = __float2bfloat16(x), hy = __float2bfloat16(y);
    bf16 lx = __float2bfloat16(x - __bfloat162float(hx));
    bf16 ly = __float2bfloat16(y - __bfloat162float(hy));
    h = pk(hx, hy); l = pk(lx, ly);
}
__device__ __forceinline__ void cp16(void* dst, const void* src) {
    unsigned d = smaddr(dst);
    asm volatile("cp.async.cg.shared.global [%0],[%1],16;\n" :: "r"(d), "l"(src) : "memory");
}
__device__ __forceinline__ void cp_commit() {
    asm volatile("cp.async.commit_group;\n" ::: "memory");
}
template<int N> __device__ __forceinline__ void cp_wait() {
    asm volatile("cp.async.wait_group %0;\n" :: "n"(N) : "memory");
}

// ---------------------------------------------------------------------------
// Pre-pass: split fp32 tensor into bf16 hi/lo planes. One float4 per thread.
// ---------------------------------------------------------------------------
__global__ void __launch_bounds__(256) split_pass(const float4* __restrict__ X,
                                                  uint2* __restrict__ H,
                                                  uint2* __restrict__ L)
{
    size_t i = (size_t)blockIdx.x * 256 + threadIdx.x;
    float4 v = X[i];
    unsigned h0, l0, h1, l1;
    split2(v.x, v.y, h0, l0); split2(v.z, v.w, h1, l1);
    H[i] = make_uint2(h0, h1);
    L[i] = make_uint2(l0, l1);
}

// ---------------------------------------------------------------------------
// GEMM: C[M,N] = A[M,K] @ W[N,K]^T + bias, bf16-split planes, cp.async 2-stage.
// BM=128 BN=128 BK=32, 256 thr = 8 warps (2M x 4N), warp tile 64x32.
// GATHER_A: A planes are head-split [(b,h),s,d].  SPLIT_C: write planes head-split.
// smem: 2 stages x 4 planes(Ah,Al,Wh,Wl) x 128x40 bf16 = 81920 B
// ---------------------------------------------------------------------------
#define GEMM_SMEM (2*4*128*40*2)

template<bool GATHER_A, bool SPLIT_C>
__global__ void __launch_bounds__(256, 2) gemm2(const bf16* __restrict__ Ah_g,
                                                const bf16* __restrict__ Al_g,
                                                const bf16* __restrict__ Wh_g,
                                                const bf16* __restrict__ Wl_g,
                                                const float* __restrict__ bias,
                                                float* __restrict__ Cf,
                                                bf16* __restrict__ Ch,
                                                bf16* __restrict__ Cl)
{
    extern __shared__ bf16 smg[];   // [stage 2][plane 4][128][40]
    const int tid = threadIdx.x, lane = tid & 31, warp = tid >> 5;
    const int wm = warp & 1, wn = warp >> 1;
    const int bm = blockIdx.x * 128, bn = blockIdx.y * 128;

    float acc[4][4][4];
#pragma unroll
    for (int i = 0; i < 4; i++)
#pragma unroll
        for (int j = 0; j < 4; j++)
#pragma unroll
            for (int k = 0; k < 4; k++) acc[i][j][k] = 0.f;

    const int lrow = tid >> 2, lch = tid & 3;   // loader: 64 rows per r, 4 chunks/row

    // stage loader: 8 x cp16 per thread (A: r0..3, W: r4..7)
    auto load_stage = [&](int st, int kt) {
#pragma unroll
        for (int r = 0; r < 4; r++) {
            int pl = r >> 1;                       // 0=Ah,1=Al
            int row = (r & 1) * 64 + lrow;
            const bf16* base = pl ? Al_g : Ah_g;
            const bf16* src;
            if (GATHER_A) {
                int m = bm + row, b = m >> 11, s = m & (SS - 1);
                int h = kt >> 6, d0 = (kt & 63) + lch * 8;
                src = base + (((size_t)(b * HH + h)) * SS + s) * DEP + d0;
            } else {
                src = base + (size_t)(bm + row) * DM + kt + lch * 8;
            }
            cp16(&smg[(((st * 4 + pl) * 128) + row) * 40 + lch * 8], src);
        }
#pragma unroll
        for (int r = 0; r < 4; r++) {
            int pl = 2 + (r >> 1);                 // 2=Wh,3=Wl
            int row = (r & 1) * 64 + lrow;
            const bf16* base = (pl == 2) ? Wh_g : Wl_g;
            const bf16* src = base + (size_t)(bn + row) * DM + kt + lch * 8;
            cp16(&smg[(((st * 4 + pl) * 128) + row) * 40 + lch * 8], src);
        }
    };

    load_stage(0, 0);
    cp_commit();

    const int NT = DM / 32;
    for (int t = 0; t < NT; t++) {
        int st = t & 1;
        if (t + 1 < NT) { load_stage(st ^ 1, (t + 1) * 32); cp_commit(); cp_wait<1>(); }
        else           { cp_wait<0>(); }
        __syncthreads();

        const bf16* As_h = &smg[(st * 4 + 0) * 128 * 40];
        const bf16* As_l = &smg[(st * 4 + 1) * 128 * 40];
        const bf16* Ws_h = &smg[(st * 4 + 2) * 128 * 40];
        const bf16* Ws_l = &smg[(st * 4 + 3) * 128 * 40];

#pragma unroll
        for (int ch = 0; ch < 2; ch++) {
            unsigned ah[4][4], al[4][4];
            int acol = ch * 16 + ((lane & 16) >> 1);
#pragma unroll
            for (int mt = 0; mt < 4; mt++) {
                int arow = wm * 64 + mt * 16 + (lane & 15);
                ldm4(ah[mt], &As_h[arow * 40 + acol]);
                ldm4(al[mt], &As_l[arow * 40 + acol]);
            }
#pragma unroll
            for (int np = 0; np < 2; np++) {
                unsigned bh4[4], bl4[4];
                int nrow = wn * 32 + np * 16 + (lane & 7) + ((lane & 16) >> 1);
                int kcol = ch * 16 + (lane & 8);
                ldm4(bh4, &Ws_h[nrow * 40 + kcol]);
                ldm4(bl4, &Ws_l[nrow * 40 + kcol]);
#pragma unroll
                for (int mt = 0; mt < 4; mt++)
#pragma unroll
                    for (int s = 0; s < 2; s++) {
                        int nt = np * 2 + s;
                        mma_bf(acc[mt][nt], ah[mt], &bh4[s * 2]);
                        mma_bf(acc[mt][nt], al[mt], &bh4[s * 2]);
                        mma_bf(acc[mt][nt], ah[mt], &bl4[s * 2]);
                    }
            }
        }
        __syncthreads();
    }

    const int g = lane >> 2, tig = lane & 3;
#pragma unroll
    for (int mt = 0; mt < 4; mt++)
#pragma unroll
        for (int nt = 0; nt < 4; nt++) {
            int m0 = bm + wm * 64 + mt * 16 + g;
            int n0 = bn + wn * 32 + nt * 8 + tig * 2;
            float b0 = bias[n0], b1 = bias[n0 + 1];
            float v00 = acc[mt][nt][0] + b0, v01 = acc[mt][nt][1] + b1;
            float v10 = acc[mt][nt][2] + b0, v11 = acc[mt][nt][3] + b1;
            if (SPLIT_C) {
                int b = m0 >> 11, s0 = m0 & (SS - 1);
                int h = n0 >> 6, d = n0 & 63;
                size_t base = (((size_t)(b * HH + h)) * SS + s0) * DEP + d;
                unsigned hh, ll;
                split2(v00, v01, hh, ll);
                *(unsigned*)&Ch[base] = hh;  *(unsigned*)&Cl[base] = ll;
                split2(v10, v11, hh, ll);
                *(unsigned*)&Ch[base + 8 * DEP] = hh;  *(unsigned*)&Cl[base + 8 * DEP] = ll;
            } else {
                *(float2*)&Cf[(size_t)m0 * DM + n0] = make_float2(v00, v01);
                *(float2*)&Cf[(size_t)(m0 + 8) * DM + n0] = make_float2(v10, v11);
            }
        }
}

// ---------------------------------------------------------------------------
// Flash attention, bf16 planes in (head-split), ctx planes out (head-split).
// q-tile 128 (16/warp), kv-tile 64, cp.async 2-stage K/V ring.
// smem: Q 2x128x72 + ring 2 stages x 4 planes x 64x72 = 110592 B
// ---------------------------------------------------------------------------
#define ATTN_SMEM ((2*128*72 + 2*4*64*72) * 2)

__global__ void __launch_bounds__(256, 2) attn2(const bf16* __restrict__ Qh_g,
                                                const bf16* __restrict__ Ql_g,
                                                const bf16* __restrict__ Kh_g,
                                                const bf16* __restrict__ Kl_g,
                                                const bf16* __restrict__ Vh_g,
                                                const bf16* __restrict__ Vl_g,
                                                bf16* __restrict__ Ch,
                                                bf16* __restrict__ Cl)
{
    extern __shared__ bf16 smb[];
    bf16* Qs_h = smb;                 // [128][72]
    bf16* Qs_l = Qs_h + 128 * 72;
    bf16* ring = Qs_l + 128 * 72;     // [2][4][64*72]  planes: Kh,Kl,Vh,Vl

    const int tid = threadIdx.x, lane = tid & 31, warp = tid >> 5;
    const int bh = blockIdx.y, q0 = blockIdx.x * 128;
    const size_t hbase = (size_t)bh * SS * DEP;

    // stage Q planes, exact x0.125 scaling (exponent-only on bf16)
    {
        const __nv_bfloat162 s8 = __float2bfloat162_rn(0.125f);
#pragma unroll
        for (int r = 0; r < 8; r++) {
            int pl = r >> 2;
            int row = ((tid + r * 256) >> 3) & 127;
            int ch = tid & 7;
            const bf16* src = (pl ? Ql_g : Qh_g) + hbase + (size_t)(q0 + row) * DEP + ch * 8;
            uint4 v = *(const uint4*)src;
            __nv_bfloat162* p = (__nv_bfloat162*)&v;
#pragma unroll
            for (int j = 0; j < 4; j++) p[j] = __hmul2(p[j], s8);
            *(uint4*)((pl ? Qs_l : Qs_h) + row * 72 + ch * 8) = v;
        }
    }
    __syncthreads();

    float oacc[8][4];
#pragma unroll
    for (int i = 0; i < 8; i++)
#pragma unroll
        for (int j = 0; j < 4; j++) oacc[i][j] = 0.f;
    float mst[2] = {-1e30f, -1e30f}, lst[2] = {0.f, 0.f};
    const int g = lane >> 2, tig = lane & 3;

    // KV stage loader: 8 x cp16 per thread
    auto load_kv = [&](int st, int k0) {
#pragma unroll
        for (int r = 0; r < 8; r++) {
            int pl = r >> 1;                     // 0=Kh,1=Kl,2=Vh,3=Vl
            int row = (r & 1) * 32 + (tid >> 3);
            int ch = tid & 7;
            const bf16* base = (pl == 0) ? Kh_g : (pl == 1) ? Kl_g : (pl == 2) ? Vh_g : Vl_g;
            const bf16* src = base + hbase + (size_t)(k0 + row) * DEP + ch * 8;
            cp16(ring + (size_t)(st * 4 + pl) * (64 * 72) + row * 72 + ch * 8, src);
        }
    };

    load_kv(0, 0);
    cp_commit();

    const int NT = SS / 64;
    for (int kt = 0; kt < NT; kt++) {
        int st = kt & 1;
        if (kt + 1 < NT) { load_kv(st ^ 1, (kt + 1) * 64); cp_commit(); cp_wait<1>(); }
        else            { cp_wait<0>(); }
        __syncthreads();

        const bf16* Ks_h = ring + (size_t)(st * 4 + 0) * (64 * 72);
        const bf16* Ks_l = ring + (size_t)(st * 4 + 1) * (64 * 72);
        const bf16* Vs_h = ring + (size_t)(st * 4 + 2) * (64 * 72);
        const bf16* Vs_l = ring + (size_t)(st * 4 + 3) * (64 * 72);

        // S = Q K^T
        float sc[8][4];
#pragma unroll
        for (int i = 0; i < 8; i++)
#pragma unroll
            for (int j = 0; j < 4; j++) sc[i][j] = 0.f;

#pragma unroll
        for (int ch = 0; ch < 4; ch++) {
            unsigned ah[4], al[4];
            int arow = warp * 16 + (lane & 15);
            int acol = ch * 16 + ((lane & 16) >> 1);
            ldm4(ah, &Qs_h[arow * 72 + acol]);
            ldm4(al, &Qs_l[arow * 72 + acol]);
#pragma unroll
            for (int np = 0; np < 4; np++) {
                unsigned bh4[4], bl4[4];
                int nrow = np * 16 + (lane & 7) + ((lane & 16) >> 1);
                int kcol = ch * 16 + (lane & 8);
                ldm4(bh4, &Ks_h[nrow * 72 + kcol]);
                ldm4(bl4, &Ks_l[nrow * 72 + kcol]);
#pragma unroll
                for (int s = 0; s < 2; s++) {
                    int nt = np * 2 + s;
                    mma_bf(sc[nt], ah, &bh4[s * 2]);
                    mma_bf(sc[nt], al, &bh4[s * 2]);
                    mma_bf(sc[nt], ah, &bl4[s * 2]);
                }
            }
        }

        // online softmax: thread owns rows g (half 0) and g+8 (half 1)
#pragma unroll
        for (int hf = 0; hf < 2; hf++) {
            float mloc = -1e30f;
#pragma unroll
            for (int nt = 0; nt < 8; nt++)
                mloc = fmaxf(mloc, fmaxf(sc[nt][hf * 2], sc[nt][hf * 2 + 1]));
            mloc = fmaxf(mloc, __shfl_xor_sync(0xffffffffu, mloc, 1));
            mloc = fmaxf(mloc, __shfl_xor_sync(0xffffffffu, mloc, 2));
            float mnew = fmaxf(mst[hf], mloc);
            float fct = __expf(mst[hf] - mnew);
            mst[hf] = mnew;
            float lloc = 0.f;
#pragma unroll
            for (int nt = 0; nt < 8; nt++) {
                float e0 = __expf(sc[nt][hf * 2] - mnew);
                float e1 = __expf(sc[nt][hf * 2 + 1] - mnew);
                sc[nt][hf * 2] = e0; sc[nt][hf * 2 + 1] = e1;
                lloc += e0 + e1;
            }
            lloc += __shfl_xor_sync(0xffffffffu, lloc, 1);
            lloc += __shfl_xor_sync(0xffffffffu, lloc, 2);
            lst[hf] = lst[hf] * fct + lloc;
#pragma unroll
            for (int dt = 0; dt < 8; dt++) {
                oacc[dt][hf * 2] *= fct;
                oacc[dt][hf * 2 + 1] *= fct;
            }
        }

        // O += P V  (P a-frags built directly from S c-frags in registers)
#pragma unroll
        for (int ch = 0; ch < 4; ch++) {
            unsigned ph[4], pl4[4];
            split2(sc[ch * 2][0],     sc[ch * 2][1],     ph[0], pl4[0]);
            split2(sc[ch * 2][2],     sc[ch * 2][3],     ph[1], pl4[1]);
            split2(sc[ch * 2 + 1][0], sc[ch * 2 + 1][1], ph[2], pl4[2]);
            split2(sc[ch * 2 + 1][2], sc[ch * 2 + 1][3], ph[3], pl4[3]);
#pragma unroll
            for (int dp = 0; dp < 4; dp++) {
                unsigned vh4[4], vl4[4];
                int krow = ch * 16 + (lane & 7) + (lane & 8);
                int dcol = dp * 16 + ((lane & 16) >> 1);
                ldm4t(vh4, &Vs_h[krow * 72 + dcol]);
                ldm4t(vl4, &Vs_l[krow * 72 + dcol]);
#pragma unroll
                for (int s = 0; s < 2; s++) {
                    int dt = dp * 2 + s;
                    mma_bf(oacc[dt], ph,  &vh4[s * 2]);
                    mma_bf(oacc[dt], pl4, &vh4[s * 2]);
                    mma_bf(oacc[dt], ph,  &vl4[s * 2]);
                }
            }
        }
        __syncthreads();
    }

    // epilogue: normalize, split into ctx planes (head-split layout)
    float inv0 = 1.0f / lst[0], inv1 = 1.0f / lst[1];
    int r0 = q0 + warp * 16 + g;
#pragma unroll
    for (int dt = 0; dt < 8; dt++) {
        int col = dt * 8 + tig * 2;
        size_t base0 = hbase + (size_t)r0 * DEP + col;
        size_t base1 = hbase + (size_t)(r0 + 8) * DEP + col;
        unsigned hh, ll;
        split2(oacc[dt][0] * inv0, oacc[dt][1] * inv0, hh, ll);
        *(unsigned*)&Ch[base0] = hh; *(unsigned*)&Cl[base0] = ll;
        split2(oacc[dt][2] * inv1, oacc[dt][3] * inv1, hh, ll);
        *(unsigned*)&Ch[base1] = hh; *(unsigned*)&Cl[base1] = ll;
    }
}

// ---------------------------------------------------------------------------
extern "C" void kernel_launch(void* const* d_in, const int* in_sizes, int n_in,
                              void* d_out, int out_size)
{
    const float* query   = (const float*)d_in[0];
    const float* key     = (const float*)d_in[1];
    const float* value   = (const float*)d_in[2];
    const float* wq_w    = (const float*)d_in[3];
    const float* wq_b    = (const float*)d_in[4];
    const float* wk_w    = (const float*)d_in[5];
    const float* wk_b    = (const float*)d_in[6];
    const float* wv_w    = (const float*)d_in[7];
    const float* wv_b    = (const float*)d_in[8];
    const float* dense_w = (const float*)d_in[9];
    const float* dense_b = (const float*)d_in[10];
    float* out = (float*)d_out;

    bf16 *xqh, *xql, *xkh, *xkl, *xvh, *xvl;
    bf16 *wqh, *wql, *wkh, *wkl, *wvh, *wvl, *wdh, *wdl;
    bf16 *Qh, *Ql, *Kh, *Kl, *Vh, *Vl, *Ch, *Cl;
    cudaGetSymbolAddress((void**)&xqh, g_xq_h); cudaGetSymbolAddress((void**)&xql, g_xq_l);
    cudaGetSymbolAddress((void**)&xkh, g_xk_h); cudaGetSymbolAddress((void**)&xkl, g_xk_l);
    cudaGetSymbolAddress((void**)&xvh, g_xv_h); cudaGetSymbolAddress((void**)&xvl, g_xv_l);
    cudaGetSymbolAddress((void**)&wqh, g_wq_h); cudaGetSymbolAddress((void**)&wql, g_wq_l);
    cudaGetSymbolAddress((void**)&wkh, g_wk_h); cudaGetSymbolAddress((void**)&wkl, g_wk_l);
    cudaGetSymbolAddress((void**)&wvh, g_wv_h); cudaGetSymbolAddress((void**)&wvl, g_wv_l);
    cudaGetSymbolAddress((void**)&wdh, g_wd_h); cudaGetSymbolAddress((void**)&wdl, g_wd_l);
    cudaGetSymbolAddress((void**)&Qh, g_Qh); cudaGetSymbolAddress((void**)&Ql, g_Ql);
    cudaGetSymbolAddress((void**)&Kh, g_Kh); cudaGetSymbolAddress((void**)&Kl, g_Kl);
    cudaGetSymbolAddress((void**)&Vh, g_Vh); cudaGetSymbolAddress((void**)&Vl, g_Vl);
    cudaGetSymbolAddress((void**)&Ch, g_Ch); cudaGetSymbolAddress((void**)&Cl, g_Cl);

    // pre-pass splits
    const int NB_X = (MR * DM / 4) / 256;   // 8192 blocks
    const int NB_W = (DM * DM / 4) / 256;   // 1024 blocks
    split_pass<<<NB_X, 256>>>((const float4*)query, (uint2*)xqh, (uint2*)xql);
    split_pass<<<NB_X, 256>>>((const float4*)key,   (uint2*)xkh, (uint2*)xkl);
    split_pass<<<NB_X, 256>>>((const float4*)value, (uint2*)xvh, (uint2*)xvl);
    split_pass<<<NB_W, 256>>>((const float4*)wq_w, (uint2*)wqh, (uint2*)wql);
    split_pass<<<NB_W, 256>>>((const float4*)wk_w, (uint2*)wkh, (uint2*)wkl);
    split_pass<<<NB_W, 256>>>((const float4*)wv_w, (uint2*)wvh, (uint2*)wvl);
    split_pass<<<NB_W, 256>>>((const float4*)dense_w, (uint2*)wdh, (uint2*)wdl);

    cudaFuncSetAttribute(gemm2<false, true>,
                         cudaFuncAttributeMaxDynamicSharedMemorySize, GEMM_SMEM);
    cudaFuncSetAttribute(gemm2<true, false>,
                         cudaFuncAttributeMaxDynamicSharedMemorySize, GEMM_SMEM);
    cudaFuncSetAttribute(attn2,
                         cudaFuncAttributeMaxDynamicSharedMemorySize, ATTN_SMEM);

    // Q/K/V projections -> split planes (head-split layout)
    dim3 gg(MR / 128, DM / 128);
    gemm2<false, true><<<gg, 256, GEMM_SMEM>>>(xqh, xql, wqh, wql, wq_b, nullptr, Qh, Ql);
    gemm2<false, true><<<gg, 256, GEMM_SMEM>>>(xkh, xkl, wkh, wkl, wk_b, nullptr, Kh, Kl);
    gemm2<false, true><<<gg, 256, GEMM_SMEM>>>(xvh, xvl, wvh, wvl, wv_b, nullptr, Vh, Vl);

    // attention -> ctx planes
    dim3 ga(SS / 128, BB * HH);
    attn2<<<ga, 256, ATTN_SMEM>>>(Qh, Ql, Kh, Kl, Vh, Vl, Ch, Cl);

    // dense projection (gather ctx planes) -> fp32 out
    gemm2<true, false><<<gg, 256, GEMM_SMEM>>>(Ch, Cl, wdh, wdl, dense_b, out, nullptr, nullptr);
}

// round 16
// speedup vs baseline: 3.1943x; 1.0331x over previous
#include <cuda_runtime.h>
#include <cuda_bf16.h>
#include <cstdint>

#define BB   4
#define SS   2048
#define HH   16
#define DEP  64
#define DM   1024
#define MR   (BB*SS)   // 8192

typedef __nv_bfloat16 bf16;

// ---------------- persistent bf16 hi/lo planes (device globals) ----------------
__device__ bf16 g_xq_h[(size_t)MR*DM], g_xq_l[(size_t)MR*DM];
__device__ bf16 g_xk_h[(size_t)MR*DM], g_xk_l[(size_t)MR*DM];
__device__ bf16 g_xv_h[(size_t)MR*DM], g_xv_l[(size_t)MR*DM];
__device__ bf16 g_wq_h[(size_t)DM*DM], g_wq_l[(size_t)DM*DM];
__device__ bf16 g_wk_h[(size_t)DM*DM], g_wk_l[(size_t)DM*DM];
__device__ bf16 g_wv_h[(size_t)DM*DM], g_wv_l[(size_t)DM*DM];
__device__ bf16 g_wd_h[(size_t)DM*DM], g_wd_l[(size_t)DM*DM];
__device__ bf16 g_Qh[(size_t)MR*DM], g_Ql[(size_t)MR*DM];   // head-split
__device__ bf16 g_Kh[(size_t)MR*DM], g_Kl[(size_t)MR*DM];   // head-split
__device__ bf16 g_Vh[(size_t)MR*DM], g_Vl[(size_t)MR*DM];   // head-split
__device__ bf16 g_Ch[(size_t)MR*DM], g_Cl[(size_t)MR*DM];   // head-split ctx

// ---------------- PTX helpers ----------------
__device__ __forceinline__ unsigned smaddr(const void* p) {
    return (unsigned)__cvta_generic_to_shared(p);
}
__device__ __forceinline__ void ldm4(unsigned r[4], const void* p) {
    unsigned a = smaddr(p);
    asm volatile("ldmatrix.sync.aligned.m8n8.x4.shared.b16 {%0,%1,%2,%3},[%4];\n"
                 : "=r"(r[0]), "=r"(r[1]), "=r"(r[2]), "=r"(r[3]) : "r"(a));
}
__device__ __forceinline__ void ldm4t(unsigned r[4], const void* p) {
    unsigned a = smaddr(p);
    asm volatile("ldmatrix.sync.aligned.m8n8.x4.trans.shared.b16 {%0,%1,%2,%3},[%4];\n"
                 : "=r"(r[0]), "=r"(r[1]), "=r"(r[2]), "=r"(r[3]) : "r"(a));
}
__device__ __forceinline__ void mma_bf(float c[4], const unsigned a[4], const unsigned b[2]) {
    asm volatile("mma.sync.aligned.m16n8k16.row.col.f32.bf16.bf16.f32 "
                 "{%0,%1,%2,%3},{%4,%5,%6,%7},{%8,%9},{%0,%1,%2,%3};\n"
                 : "+f"(c[0]), "+f"(c[1]), "+f"(c[2]), "+f"(c[3])
                 : "r"(a[0]), "r"(a[1]), "r"(a[2]), "r"(a[3]), "r"(b[0]), "r"(b[1]));
}
__device__ __forceinline__ unsigned pk(bf16 a, bf16 b) {
    return (unsigned)__bfloat16_as_ushort(a) | ((unsigned)__bfloat16_as_ushort(b) << 16);
}
__device__ __forceinline__ void split2(float x, float y, unsigned& h, unsigned& l) {
    bf16 hx = __float2bfloat16(x), hy = __float2bfloat16(y);
    bf16 lx = __float2bfloat16(x - __bfloat162float(hx));
    bf16 ly = __float2bfloat16(y - __bfloat162float(hy));
    h = pk(hx, hy); l = pk(lx, ly);
}
__device__ __forceinline__ void cp16(void* dst, const void* src) {
    unsigned d = smaddr(dst);
    asm volatile("cp.async.cg.shared.global [%0],[%1],16;\n" :: "r"(d), "l"(src) : "memory");
}
__device__ __forceinline__ void cp_commit() {
    asm volatile("cp.async.commit_group;\n" ::: "memory");
}
template<int N> __device__ __forceinline__ void cp_wait() {
    asm volatile("cp.async.wait_group %0;\n" :: "n"(N) : "memory");
}

// ---------------------------------------------------------------------------
// Fused pre-pass: split all 7 fp32 tensors into bf16 hi/lo planes, one launch.
// ---------------------------------------------------------------------------
#define XB ((MR*DM/4)/256)   // 8192 blocks per X tensor
#define WB ((DM*DM/4)/256)   // 1024 blocks per W tensor

__global__ void __launch_bounds__(256) split_all(
    const float4* __restrict__ q,  const float4* __restrict__ k,
    const float4* __restrict__ v,  const float4* __restrict__ wq,
    const float4* __restrict__ wk, const float4* __restrict__ wv,
    const float4* __restrict__ wd,
    uint2* qh, uint2* ql, uint2* kh, uint2* kl, uint2* vh, uint2* vl,
    uint2* wqh, uint2* wql, uint2* wkh, uint2* wkl,
    uint2* wvh, uint2* wvl, uint2* wdh, uint2* wdl)
{
    int id = blockIdx.x;
    const float4* src; uint2 *H, *L; int lid;
    if      (id < 1*XB) { src = q;  H = qh;  L = ql;  lid = id; }
    else if (id < 2*XB) { src = k;  H = kh;  L = kl;  lid = id - 1*XB; }
    else if (id < 3*XB) { src = v;  H = vh;  L = vl;  lid = id - 2*XB; }
    else {
        id -= 3*XB;
        if      (id < 1*WB) { src = wq; H = wqh; L = wql; lid = id; }
        else if (id < 2*WB) { src = wk; H = wkh; L = wkl; lid = id - 1*WB; }
        else if (id < 3*WB) { src = wv; H = wvh; L = wvl; lid = id - 2*WB; }
        else                { src = wd; H = wdh; L = wdl; lid = id - 3*WB; }
    }
    size_t i = (size_t)lid * 256 + threadIdx.x;
    float4 x = src[i];
    unsigned h0, l0, h1, l1;
    split2(x.x, x.y, h0, l0); split2(x.z, x.w, h1, l1);
    H[i] = make_uint2(h0, h1);
    L[i] = make_uint2(l0, l1);
}

// ---------------------------------------------------------------------------
// GEMM: C[M,N] = A[M,K] @ W[N,K]^T + bias, bf16-split (3 mma), cp.async 2-stage.
// CTA 128x128, 128 threads = 4 warps (2M x 2N), warp tile 64x64. BK=32.
// smem: 2 stages x 4 planes x 128x40 bf16 = 81920 B -> 2 CTAs/SM.
// ---------------------------------------------------------------------------
#define GEMM_SMEM (2*4*128*40*2)

template<bool GATHER_A, bool SPLIT_C>
__global__ void __launch_bounds__(128, 2) gemm3(const bf16* __restrict__ Ah_g,
                                                const bf16* __restrict__ Al_g,
                                                const bf16* __restrict__ Wh_g,
                                                const bf16* __restrict__ Wl_g,
                                                const float* __restrict__ bias,
                                                float* __restrict__ Cf,
                                                bf16* __restrict__ Ch,
                                                bf16* __restrict__ Cl)
{
    extern __shared__ bf16 smg[];   // [stage 2][plane 4][128][40]
    const int tid = threadIdx.x, lane = tid & 31, warp = tid >> 5;
    const int wm = warp >> 1, wn = warp & 1;
    const int bm = blockIdx.x * 128, bn = blockIdx.y * 128;

    float acc[4][8][4];
#pragma unroll
    for (int i = 0; i < 4; i++)
#pragma unroll
        for (int j = 0; j < 8; j++)
#pragma unroll
            for (int kk = 0; kk < 4; kk++) acc[i][j][kk] = 0.f;

    // stage loader: 4 planes x (128 rows x 4 chunks of 16B) = 2048 cp16 / 128 thr
    auto load_stage = [&](int st, int kt) {
#pragma unroll
        for (int r = 0; r < 16; r++) {
            int pl = r >> 2;                   // 0=Ah,1=Al,2=Wh,3=Wl
            int c = (r & 3) * 128 + tid;       // 0..511
            int row = c >> 2, ch = c & 3;
            bf16* dst = &smg[(((st * 4 + pl) * 128) + row) * 40 + ch * 8];
            const bf16* src;
            if (pl < 2) {
                const bf16* base = pl ? Al_g : Ah_g;
                if (GATHER_A) {
                    int m = bm + row, b = m >> 11, s = m & (SS - 1), h = kt >> 6;
                    src = base + (((size_t)(b * HH + h)) * SS + s) * DEP + (kt & 63) + ch * 8;
                } else {
                    src = base + (size_t)(bm + row) * DM + kt + ch * 8;
                }
            } else {
                const bf16* base = (pl == 2) ? Wh_g : Wl_g;
                src = base + (size_t)(bn + row) * DM + kt + ch * 8;
            }
            cp16(dst, src);
        }
    };

    load_stage(0, 0);
    cp_commit();

    const int NT = DM / 32;    // 32 stages
    for (int t = 0; t < NT; t++) {
        int st = t & 1;
        if (t + 1 < NT) { load_stage(st ^ 1, (t + 1) * 32); cp_commit(); cp_wait<1>(); }
        else           { cp_wait<0>(); }
        __syncthreads();

        const bf16* As_h = &smg[(st * 4 + 0) * 128 * 40];
        const bf16* As_l = &smg[(st * 4 + 1) * 128 * 40];
        const bf16* Ws_h = &smg[(st * 4 + 2) * 128 * 40];
        const bf16* Ws_l = &smg[(st * 4 + 3) * 128 * 40];

#pragma unroll
        for (int ch = 0; ch < 2; ch++) {
            unsigned ah[4][4], al[4][4];
            int acol = ch * 16 + ((lane & 16) >> 1);
#pragma unroll
            for (int mt = 0; mt < 4; mt++) {
                int arow = wm * 64 + mt * 16 + (lane & 15);
                ldm4(ah[mt], &As_h[arow * 40 + acol]);
                ldm4(al[mt], &As_l[arow * 40 + acol]);
            }
#pragma unroll
            for (int np = 0; np < 4; np++) {
                unsigned bh4[4], bl4[4];
                int nrow = wn * 64 + np * 16 + (lane & 7) + ((lane & 16) >> 1);
                int kcol = ch * 16 + (lane & 8);
                ldm4(bh4, &Ws_h[nrow * 40 + kcol]);
                ldm4(bl4, &Ws_l[nrow * 40 + kcol]);
#pragma unroll
                for (int s = 0; s < 2; s++) {
                    int nt = np * 2 + s;
#pragma unroll
                    for (int mt = 0; mt < 4; mt++) {
                        mma_bf(acc[mt][nt], ah[mt], &bh4[s * 2]);
                        mma_bf(acc[mt][nt], al[mt], &bh4[s * 2]);
                        mma_bf(acc[mt][nt], ah[mt], &bl4[s * 2]);
                    }
                }
            }
        }
        __syncthreads();
    }

    const int g = lane >> 2, tig = lane & 3;
#pragma unroll
    for (int mt = 0; mt < 4; mt++)
#pragma unroll
        for (int nt = 0; nt < 8; nt++) {
            int m0 = bm + wm * 64 + mt * 16 + g;
            int n0 = bn + wn * 64 + nt * 8 + tig * 2;
            float b0 = bias[n0], b1 = bias[n0 + 1];
            float v00 = acc[mt][nt][0] + b0, v01 = acc[mt][nt][1] + b1;
            float v10 = acc[mt][nt][2] + b0, v11 = acc[mt][nt][3] + b1;
            if (SPLIT_C) {
                int b = m0 >> 11, s0 = m0 & (SS - 1);
                int h = n0 >> 6, d = n0 & 63;
                size_t base = (((size_t)(b * HH + h)) * SS + s0) * DEP + d;
                unsigned hh, ll;
                split2(v00, v01, hh, ll);
                *(unsigned*)&Ch[base] = hh;  *(unsigned*)&Cl[base] = ll;
                split2(v10, v11, hh, ll);
                *(unsigned*)&Ch[base + 8 * DEP] = hh;  *(unsigned*)&Cl[base + 8 * DEP] = ll;
            } else {
                *(float2*)&Cf[(size_t)m0 * DM + n0] = make_float2(v00, v01);
                *(float2*)&Cf[(size_t)(m0 + 8) * DM + n0] = make_float2(v10, v11);
            }
        }
}

// ---------------------------------------------------------------------------
// Flash attention, bf16-split mma. 128 thr = 4 warps; 32 q-rows/warp (mt=2),
// q-tile 128, kv-tile 64, cp.async 2-stage ring. V frags shared across m-tiles.
// smem: Q 2x128x72 + ring 2x4x64x72 bf16 = 110592 B -> 2 CTAs/SM.
// ---------------------------------------------------------------------------
#define ATTN_SMEM ((2*128*72 + 2*4*64*72) * 2)

__global__ void __launch_bounds__(128, 2) attn3(const bf16* __restrict__ Qh_g,
                                                const bf16* __restrict__ Ql_g,
                                                const bf16* __restrict__ Kh_g,
                                                const bf16* __restrict__ Kl_g,
                                                const bf16* __restrict__ Vh_g,
                                                const bf16* __restrict__ Vl_g,
                                                bf16* __restrict__ Ch,
                                                bf16* __restrict__ Cl)
{
    extern __shared__ bf16 smb[];
    bf16* Qs_h = smb;                 // [128][72]
    bf16* Qs_l = Qs_h + 128 * 72;
    bf16* ring = Qs_l + 128 * 72;     // [2][4][64*72]  planes: Kh,Kl,Vh,Vl

    const int tid = threadIdx.x, lane = tid & 31, warp = tid >> 5;
    const int bh = blockIdx.y, q0 = blockIdx.x * 128;
    const size_t hbase = (size_t)bh * SS * DEP;

    // stage Q planes, exact x0.125 scaling
    {
        const __nv_bfloat162 s8 = __float2bfloat162_rn(0.125f);
#pragma unroll
        for (int r = 0; r < 16; r++) {
            int c = r * 128 + tid;            // 0..2047
            int pl = c >> 10;                 // 0..1
            int row = (c >> 3) & 127;
            int ch = c & 7;
            const bf16* src = (pl ? Ql_g : Qh_g) + hbase + (size_t)(q0 + row) * DEP + ch * 8;
            uint4 v = *(const uint4*)src;
            __nv_bfloat162* p = (__nv_bfloat162*)&v;
#pragma unroll
            for (int j = 0; j < 4; j++) p[j] = __hmul2(p[j], s8);
            *(uint4*)((pl ? Qs_l : Qs_h) + row * 72 + ch * 8) = v;
        }
    }
    __syncthreads();

    float oacc[2][8][4];
#pragma unroll
    for (int m = 0; m < 2; m++)
#pragma unroll
        for (int i = 0; i < 8; i++)
#pragma unroll
            for (int j = 0; j < 4; j++) oacc[m][i][j] = 0.f;
    float mst[4] = {-1e30f, -1e30f, -1e30f, -1e30f};
    float lst[4] = {0.f, 0.f, 0.f, 0.f};
    const int g = lane >> 2, tig = lane & 3;

    // KV stage loader: 4 planes x (64 rows x 8 chunks) = 2048 cp16 / 128 thr
    auto load_kv = [&](int st, int k0) {
#pragma unroll
        for (int r = 0; r < 16; r++) {
            int pl = r >> 2;                   // 0=Kh,1=Kl,2=Vh,3=Vl
            int c = (r & 3) * 128 + tid;       // 0..511
            int row = c >> 3, ch = c & 7;
            const bf16* base = (pl == 0) ? Kh_g : (pl == 1) ? Kl_g : (pl == 2) ? Vh_g : Vl_g;
            const bf16* src = base + hbase + (size_t)(k0 + row) * DEP + ch * 8;
            cp16(ring + (size_t)(st * 4 + pl) * (64 * 72) + row * 72 + ch * 8, src);
        }
    };

    load_kv(0, 0);
    cp_commit();

    const int NT = SS / 64;
    for (int kt = 0; kt < NT; kt++) {
        int st = kt & 1;
        if (kt + 1 < NT) { load_kv(st ^ 1, (kt + 1) * 64); cp_commit(); cp_wait<1>(); }
        else            { cp_wait<0>(); }
        __syncthreads();

        const bf16* Ks_h = ring + (size_t)(st * 4 + 0) * (64 * 72);
        const bf16* Ks_l = ring + (size_t)(st * 4 + 1) * (64 * 72);
        const bf16* Vs_h = ring + (size_t)(st * 4 + 2) * (64 * 72);
        const bf16* Vs_l = ring + (size_t)(st * 4 + 3) * (64 * 72);

        // S = Q K^T   (two m-tiles per warp)
        float sc[2][8][4];
#pragma unroll
        for (int m = 0; m < 2; m++)
#pragma unroll
            for (int i = 0; i < 8; i++)
#pragma unroll
                for (int j = 0; j < 4; j++) sc[m][i][j] = 0.f;

#pragma unroll
        for (int ch = 0; ch < 4; ch++) {
            unsigned ah[2][4], al[2][4];
            int acol = ch * 16 + ((lane & 16) >> 1);
#pragma unroll
            for (int mt = 0; mt < 2; mt++) {
                int arow = warp * 32 + mt * 16 + (lane & 15);
                ldm4(ah[mt], &Qs_h[arow * 72 + acol]);
                ldm4(al[mt], &Qs_l[arow * 72 + acol]);
            }
#pragma unroll
            for (int np = 0; np < 4; np++) {
                unsigned bh4[4], bl4[4];
                int nrow = np * 16 + (lane & 7) + ((lane & 16) >> 1);
                int kcol = ch * 16 + (lane & 8);
                ldm4(bh4, &Ks_h[nrow * 72 + kcol]);
                ldm4(bl4, &Ks_l[nrow * 72 + kcol]);
#pragma unroll
                for (int s = 0; s < 2; s++) {
                    int nt = np * 2 + s;
#pragma unroll
                    for (int mt = 0; mt < 2; mt++) {
                        mma_bf(sc[mt][nt], ah[mt], &bh4[s * 2]);
                        mma_bf(sc[mt][nt], al[mt], &bh4[s * 2]);
                        mma_bf(sc[mt][nt], ah[mt], &bl4[s * 2]);
                    }
                }
            }
        }

        // online softmax: 4 row-states (mt x half); row group = 4 lanes (tig)
#pragma unroll
        for (int mt = 0; mt < 2; mt++)
#pragma unroll
            for (int hf = 0; hf < 2; hf++) {
                int rs = mt * 2 + hf;
                float mloc = -1e30f;
#pragma unroll
                for (int nt = 0; nt < 8; nt++)
                    mloc = fmaxf(mloc, fmaxf(sc[mt][nt][hf * 2], sc[mt][nt][hf * 2 + 1]));
                mloc = fmaxf(mloc, __shfl_xor_sync(0xffffffffu, mloc, 1));
                mloc = fmaxf(mloc, __shfl_xor_sync(0xffffffffu, mloc, 2));
                float mnew = fmaxf(mst[rs], mloc);
                float fct = __expf(mst[rs] - mnew);
                mst[rs] = mnew;
                float lloc = 0.f;
#pragma unroll
                for (int nt = 0; nt < 8; nt++) {
                    float e0 = __expf(sc[mt][nt][hf * 2] - mnew);
                    float e1 = __expf(sc[mt][nt][hf * 2 + 1] - mnew);
                    sc[mt][nt][hf * 2] = e0; sc[mt][nt][hf * 2 + 1] = e1;
                    lloc += e0 + e1;
                }
                lloc += __shfl_xor_sync(0xffffffffu, lloc, 1);
                lloc += __shfl_xor_sync(0xffffffffu, lloc, 2);
                lst[rs] = lst[rs] * fct + lloc;
#pragma unroll
                for (int dt = 0; dt < 8; dt++) {
                    oacc[mt][dt][hf * 2] *= fct;
                    oacc[mt][dt][hf * 2 + 1] *= fct;
                }
            }

        // O += P V  (P a-frags from S c-frags in registers; V frags shared over mt)
#pragma unroll
        for (int ch = 0; ch < 4; ch++) {
            unsigned ph4[2][4], pl4[2][4];
#pragma unroll
            for (int mt = 0; mt < 2; mt++) {
                split2(sc[mt][ch * 2][0],     sc[mt][ch * 2][1],     ph4[mt][0], pl4[mt][0]);
                split2(sc[mt][ch * 2][2],     sc[mt][ch * 2][3],     ph4[mt][1], pl4[mt][1]);
                split2(sc[mt][ch * 2 + 1][0], sc[mt][ch * 2 + 1][1], ph4[mt][2], pl4[mt][2]);
                split2(sc[mt][ch * 2 + 1][2], sc[mt][ch * 2 + 1][3], ph4[mt][3], pl4[mt][3]);
            }
#pragma unroll
            for (int dp = 0; dp < 4; dp++) {
                unsigned vh4[4], vl4[4];
                int krow = ch * 16 + (lane & 7) + (lane & 8);
                int dcol = dp * 16 + ((lane & 16) >> 1);
                ldm4t(vh4, &Vs_h[krow * 72 + dcol]);
                ldm4t(vl4, &Vs_l[krow * 72 + dcol]);
#pragma unroll
                for (int s = 0; s < 2; s++) {
                    int dt = dp * 2 + s;
#pragma unroll
                    for (int mt = 0; mt < 2; mt++) {
                        mma_bf(oacc[mt][dt], ph4[mt], &vh4[s * 2]);
                        mma_bf(oacc[mt][dt], pl4[mt], &vh4[s * 2]);
                        mma_bf(oacc[mt][dt], ph4[mt], &vl4[s * 2]);
                    }
                }
            }
        }
        __syncthreads();
    }

    // epilogue: normalize, split into ctx planes (head-split layout)
#pragma unroll
    for (int mt = 0; mt < 2; mt++) {
        float inv0 = 1.0f / lst[mt * 2];
        float inv1 = 1.0f / lst[mt * 2 + 1];
        int r0 = q0 + warp * 32 + mt * 16 + g;
#pragma unroll
        for (int dt = 0; dt < 8; dt++) {
            int col = dt * 8 + tig * 2;
            size_t base0 = hbase + (size_t)r0 * DEP + col;
            size_t base1 = hbase + (size_t)(r0 + 8) * DEP + col;
            unsigned hh, ll;
            split2(oacc[mt][dt][0] * inv0, oacc[mt][dt][1] * inv0, hh, ll);
            *(unsigned*)&Ch[base0] = hh; *(unsigned*)&Cl[base0] = ll;
            split2(oacc[mt][dt][2] * inv1, oacc[mt][dt][3] * inv1, hh, ll);
            *(unsigned*)&Ch[base1] = hh; *(unsigned*)&Cl[base1] = ll;
        }
    }
}

// ---------------------------------------------------------------------------
extern "C" void kernel_launch(void* const* d_in, const int* in_sizes, int n_in,
                              void* d_out, int out_size)
{
    const float* query   = (const float*)d_in[0];
    const float* key     = (const float*)d_in[1];
    const float* value   = (const float*)d_in[2];
    const float* wq_w    = (const float*)d_in[3];
    const float* wq_b    = (const float*)d_in[4];
    const float* wk_w    = (const float*)d_in[5];
    const float* wk_b    = (const float*)d_in[6];
    const float* wv_w    = (const float*)d_in[7];
    const float* wv_b    = (const float*)d_in[8];
    const float* dense_w = (const float*)d_in[9];
    const float* dense_b = (const float*)d_in[10];
    float* out = (float*)d_out;

    bf16 *xqh, *xql, *xkh, *xkl, *xvh, *xvl;
    bf16 *wqh, *wql, *wkh, *wkl, *wvh, *wvl, *wdh, *wdl;
    bf16 *Qh, *Ql, *Kh, *Kl, *Vh, *Vl, *Ch, *Cl;
    cudaGetSymbolAddress((void**)&xqh, g_xq_h); cudaGetSymbolAddress((void**)&xql, g_xq_l);
    cudaGetSymbolAddress((void**)&xkh, g_xk_h); cudaGetSymbolAddress((void**)&xkl, g_xk_l);
    cudaGetSymbolAddress((void**)&xvh, g_xv_h); cudaGetSymbolAddress((void**)&xvl, g_xv_l);
    cudaGetSymbolAddress((void**)&wqh, g_wq_h); cudaGetSymbolAddress((void**)&wql, g_wq_l);
    cudaGetSymbolAddress((void**)&wkh, g_wk_h); cudaGetSymbolAddress((void**)&wkl, g_wk_l);
    cudaGetSymbolAddress((void**)&wvh, g_wv_h); cudaGetSymbolAddress((void**)&wvl, g_wv_l);
    cudaGetSymbolAddress((void**)&wdh, g_wd_h); cudaGetSymbolAddress((void**)&wdl, g_wd_l);
    cudaGetSymbolAddress((void**)&Qh, g_Qh); cudaGetSymbolAddress((void**)&Ql, g_Ql);
    cudaGetSymbolAddress((void**)&Kh, g_Kh); cudaGetSymbolAddress((void**)&Kl, g_Kl);
    cudaGetSymbolAddress((void**)&Vh, g_Vh); cudaGetSymbolAddress((void**)&Vl, g_Vl);
    cudaGetSymbolAddress((void**)&Ch, g_Ch); cudaGetSymbolAddress((void**)&Cl, g_Cl);

    // fused split pre-pass (one launch for all 7 tensors)
    split_all<<<3 * XB + 4 * WB, 256>>>(
        (const float4*)query, (const float4*)key, (const float4*)value,
        (const float4*)wq_w, (const float4*)wk_w, (const float4*)wv_w,
        (const float4*)dense_w,
        (uint2*)xqh, (uint2*)xql, (uint2*)xkh, (uint2*)xkl, (uint2*)xvh, (uint2*)xvl,
        (uint2*)wqh, (uint2*)wql, (uint2*)wkh, (uint2*)wkl,
        (uint2*)wvh, (uint2*)wvl, (uint2*)wdh, (uint2*)wdl);

    cudaFuncSetAttribute(gemm3<false, true>,
                         cudaFuncAttributeMaxDynamicSharedMemorySize, GEMM_SMEM);
    cudaFuncSetAttribute(gemm3<true, false>,
                         cudaFuncAttributeMaxDynamicSharedMemorySize, GEMM_SMEM);
    cudaFuncSetAttribute(attn3,
                         cudaFuncAttributeMaxDynamicSharedMemorySize, ATTN_SMEM);

    dim3 gg(MR / 128, DM / 128);
    gemm3<false, true><<<gg, 128, GEMM_SMEM>>>(xqh, xql, wqh, wql, wq_b, nullptr, Qh, Ql);
    gemm3<false, true><<<gg, 128, GEMM_SMEM>>>(xkh, xkl, wkh, wkl, wk_b, nullptr, Kh, Kl);
    gemm3<false, true><<<gg, 128, GEMM_SMEM>>>(xvh, xvl, wvh, wvl, wv_b, nullptr, Vh, Vl);

    dim3 ga(SS / 128, BB * HH);
    attn3<<<ga, 128, ATTN_SMEM>>>(Qh, Ql, Kh, Kl, Vh, Vl, Ch, Cl);

    gemm3<true, false><<<gg, 128, GEMM_SMEM>>>(Ch, Cl, wdh, wdl, dense_b, out, nullptr, nullptr);
}